// round 12
// baseline (speedup 1.0000x reference)
#include <cuda_runtime.h>
#include <cuda_bf16.h>
#include <cstdint>

#define B_WIN   2048
#define NTOK    64
#define DIM     256
#define NHEADS  8
#define QKVDIM  768
#define MROWS   (B_WIN * NTOK)          // 131072
#define SCALE   0.17677669529663687f    // 32^-0.5

// ---------------- scratch (device globals; no cudaMalloc allowed) ----------
#define HEAD_ELEMS (2048ull * 8ull * 64ull * 32ull)
__device__ __nv_bfloat16 g_q_hi[HEAD_ELEMS],  g_q_lo[HEAD_ELEMS];
__device__ __nv_bfloat16 g_k_hi[HEAD_ELEMS],  g_k_lo[HEAD_ELEMS];
__device__ __nv_bfloat16 g_vt_hi[HEAD_ELEMS], g_vt_lo[HEAD_ELEMS];  // [bh][d][n]
__device__ float g_ao[(size_t)MROWS * DIM];    // tf32-rounded attention out
__device__ float g_wqr[QKVDIM * DIM];          // tf32-rounded w_qkv
__device__ float g_wpr[DIM * DIM];             // tf32-rounded w_proj

// ================= helpers ==================================================
__device__ __forceinline__ uint32_t smem_u32(const void* p) {
    uint32_t a;
    asm("{ .reg .u64 t; cvta.to.shared.u64 t, %1; cvt.u32.u64 %0, t; }"
        : "=r"(a) : "l"(p));
    return a;
}

__device__ __forceinline__ void ldsm_x4(uint32_t* r, uint32_t addr) {
    asm volatile("ldmatrix.sync.aligned.m8n8.x4.shared.b16 {%0,%1,%2,%3}, [%4];"
                 : "=r"(r[0]), "=r"(r[1]), "=r"(r[2]), "=r"(r[3]) : "r"(addr));
}

// bf16 k16 mma (attention path)
__device__ __forceinline__ void mma16816(float* c, const uint32_t* a, const uint32_t* b) {
    asm volatile("mma.sync.aligned.m16n8k16.row.col.f32.bf16.bf16.f32 "
                 "{%0,%1,%2,%3}, {%4,%5,%6,%7}, {%8,%9}, {%0,%1,%2,%3};"
                 : "+f"(c[0]), "+f"(c[1]), "+f"(c[2]), "+f"(c[3])
                 : "r"(a[0]), "r"(a[1]), "r"(a[2]), "r"(a[3]),
                   "r"(b[0]), "r"(b[1]));
}

// tf32 k8 mma (GEMM path)
__device__ __forceinline__ void mma1688(float* c, const uint32_t* a,
                                        uint32_t b0, uint32_t b1) {
    asm volatile("mma.sync.aligned.m16n8k8.row.col.f32.tf32.tf32.f32 "
                 "{%0,%1,%2,%3}, {%4,%5,%6,%7}, {%8,%9}, {%0,%1,%2,%3};"
                 : "+f"(c[0]), "+f"(c[1]), "+f"(c[2]), "+f"(c[3])
                 : "r"(a[0]), "r"(a[1]), "r"(a[2]), "r"(a[3]),
                   "r"(b0), "r"(b1));
}

__device__ __forceinline__ float tf32r(float f) {
    uint32_t u;
    asm("cvt.rna.tf32.f32 %0, %1;" : "=r"(u) : "f"(f));
    return __uint_as_float(u);
}
__device__ __forceinline__ uint32_t tf32r_bits(uint32_t fb) {
    uint32_t u;
    asm("cvt.rna.tf32.f32 %0, %1;" : "=r"(u) : "f"(__uint_as_float(fb)));
    return u;
}

__device__ __forceinline__ uint32_t pack_bf16x2(float x, float y) {
    __nv_bfloat162 t = __floats2bfloat162_rn(x, y);
    return *(uint32_t*)&t;
}

__device__ __forceinline__ void cp16(uint32_t dst, const void* src) {
    asm volatile("cp.async.cg.shared.global [%0], [%1], 16;"
                 :: "r"(dst), "l"(src) : "memory");
}
#define CP_COMMIT() asm volatile("cp.async.commit_group;" ::: "memory")

// ================= fp32 -> tf32-rounded fp32 (weights only) ================
__global__ void round_tf32(const float* __restrict__ src,
                           float* __restrict__ dst, int n4)
{
    int i = blockIdx.x * blockDim.x + threadIdx.x;
    if (i >= n4) return;
    float4 v = ((const float4*)src)[i];
    v.x = tf32r(v.x); v.y = tf32r(v.y); v.z = tf32r(v.z); v.w = tf32r(v.w);
    ((float4*)dst)[i] = v;
}

// ================= TF32 GEMM — occupancy variant ============================
// Block tile 128x64, 8 warps 4(M)x2(N), warp tile 32x32, BK=32, 2 stages.
// __launch_bounds__(256,3): 3 CTAs/SM -> 24 warps/SM (was 16).
// Same total mma count as R11 — this isolates the occupancy axis.
// A raw fp32, rounded in-register post-LDSM; W pre-rounded.

#define TSTRW  36                   // fp32 words per smem row (144B, conflict-free)
#define T_A    0
#define T_B    18432                // 128*36*4
#define TSTAGE 27648                // + 64*36*4
#define TGEMM_SMEM (2 * TSTAGE)     // 55296 bytes

template <int MODE>
__global__ void __launch_bounds__(256, 3)
gemm_tf32(const float* __restrict__ A, const float* __restrict__ W,
          const float* __restrict__ bias, float* __restrict__ out)
{
    extern __shared__ char smem[];
    const uint32_t sb = smem_u32(smem);

    const int tid  = threadIdx.x;
    const int lane = tid & 31;
    const int warp = tid >> 5;
    const int wm   = warp >> 1;          // 0..3
    const int wn   = warp & 1;           // 0..1
    const int row0 = blockIdx.y * 128;
    const int col0 = blockIdx.x * 64;

    float acc[2][4][4];
#pragma unroll
    for (int a = 0; a < 2; a++)
#pragma unroll
        for (int b = 0; b < 4; b++)
#pragma unroll
            for (int c = 0; c < 4; c++) acc[a][b][c] = 0.f;

    const int gid = lane >> 2, tig = lane & 3;

    auto issue = [&](int kc) {
        const uint32_t stb = sb + (kc & 1) * TSTAGE;
        const int k0 = kc * 32;
        // A: 128x32 fp32 = 1024 16B chunks (4/thread)
#pragma unroll
        for (int t = 0; t < 4; t++) {
            const int idx = tid + t * 256;
            const int r = idx >> 3, c8 = idx & 7;
            cp16(stb + T_A + (uint32_t)r * 144 + c8 * 16,
                 A + (size_t)(row0 + r) * 256 + k0 + c8 * 4);
        }
        // B: 64x32 fp32 = 512 chunks (2/thread)
#pragma unroll
        for (int t = 0; t < 2; t++) {
            const int idx = tid + t * 256;
            const int r = idx >> 3, c8 = idx & 7;
            cp16(stb + T_B + (uint32_t)r * 144 + c8 * 16,
                 W + (size_t)(col0 + r) * 256 + k0 + c8 * 4);
        }
        CP_COMMIT();
    };

    issue(0);

    // ldsm lane addressing (tf32 word mapping == m16n8k8 fragment layout):
    // A matrices: (rows 0-7 / 8-15) x (k 0-3 / 4-7)
    // B matrices: (rows 0-7: k 0-3, k 4-7), (rows 8-15: k 0-3, k 4-7)
    const int lg = lane >> 3, lrw = lane & 7;
    const uint32_t a_ld = (uint32_t)((wm * 32 + ((lg & 1) << 3) + lrw) * TSTRW
                                     + ((lg >> 1) << 2)) * 4;
    const uint32_t b_ld = (uint32_t)((wn * 32 + ((lg >> 1) << 3) + lrw) * TSTRW
                                     + ((lg & 1) << 2)) * 4;

    for (int kc = 0; kc < 8; kc++) {
        if (kc < 7) {
            issue(kc + 1);
            asm volatile("cp.async.wait_group 1;" ::: "memory");
        } else {
            asm volatile("cp.async.wait_group 0;" ::: "memory");
        }
        __syncthreads();

        const uint32_t sA = sb + (kc & 1) * TSTAGE + T_A;
        const uint32_t sB = sb + (kc & 1) * TSTAGE + T_B;

#pragma unroll
        for (int ks = 0; ks < 4; ks++) {
            const uint32_t kso = (uint32_t)(ks * 8) * 4;
            uint32_t af[2][4], bf[2][4];
#pragma unroll
            for (int mt = 0; mt < 2; mt++) {
                ldsm_x4(af[mt], sA + a_ld + mt * 16 * TSTRW * 4 + kso);
#pragma unroll
                for (int i = 0; i < 4; i++)       // round raw fp32 A -> tf32
                    af[mt][i] = tf32r_bits(af[mt][i]);
            }
#pragma unroll
            for (int p = 0; p < 2; p++)
                ldsm_x4(bf[p], sB + b_ld + p * 16 * TSTRW * 4 + kso);
#pragma unroll
            for (int mt = 0; mt < 2; mt++)
#pragma unroll
                for (int nt = 0; nt < 4; nt++) {
                    const uint32_t* bb = &bf[nt >> 1][(nt & 1) * 2];
                    mma1688(acc[mt][nt], af[mt], bb[0], bb[1]);
                }
        }
        __syncthreads();
    }

    // ---- epilogue -------------------------------------------------------------
#pragma unroll
    for (int mt = 0; mt < 2; mt++)
#pragma unroll
        for (int nt = 0; nt < 4; nt++) {
            const int col = col0 + wn * 32 + nt * 8 + tig * 2;
            const float2 bv = *(const float2*)(bias + col);
#pragma unroll
            for (int rs = 0; rs < 2; rs++) {
                const int row = row0 + wm * 32 + mt * 16 + gid + rs * 8;
                float v0 = acc[mt][nt][rs * 2 + 0] + bv.x;
                float v1 = acc[mt][nt][rs * 2 + 1] + bv.y;
                if (MODE == 0) {
                    const int s = col >> 8;
                    if (s == 0) { v0 *= SCALE; v1 *= SCALE; }
                    __nv_bfloat16 h0 = __float2bfloat16(v0);
                    __nv_bfloat16 l0 = __float2bfloat16(v0 - __bfloat162float(h0));
                    __nv_bfloat16 h1 = __float2bfloat16(v1);
                    __nv_bfloat16 l1 = __float2bfloat16(v1 - __bfloat162float(h1));
                    const int hh = (col >> 5) & 7, d = col & 31;
                    const int b = row >> 6, n = row & 63;
                    const size_t pb = (size_t)(b * 8 + hh) * 2048;
                    if (s == 0) {
                        *(__nv_bfloat162*)(g_q_hi + pb + n * 32 + d) = __halves2bfloat162(h0, h1);
                        *(__nv_bfloat162*)(g_q_lo + pb + n * 32 + d) = __halves2bfloat162(l0, l1);
                    } else if (s == 1) {
                        *(__nv_bfloat162*)(g_k_hi + pb + n * 32 + d) = __halves2bfloat162(h0, h1);
                        *(__nv_bfloat162*)(g_k_lo + pb + n * 32 + d) = __halves2bfloat162(l0, l1);
                    } else {   // v, stored transposed [d][n]
                        g_vt_hi[pb + (size_t)d * 64 + n]       = h0;
                        g_vt_hi[pb + (size_t)(d + 1) * 64 + n] = h1;
                        g_vt_lo[pb + (size_t)d * 64 + n]       = l0;
                        g_vt_lo[pb + (size_t)(d + 1) * 64 + n] = l1;
                    }
                } else {
                    *(float2*)(out + (size_t)row * 256 + col)
                        = make_float2(v0, v1);
                }
            }
        }
}

// ================= HMMA attention: one (window, head) per CTA ===============
#define QSTR 40
#define VSTR 72

__global__ void __launch_bounds__(128)
attn_mma(const float* __restrict__ mask, const float* __restrict__ bias_table)
{
    const int bh = blockIdx.x;
    const int b  = bh >> 3;
    const int h  = bh & 7;

    __shared__ __nv_bfloat16 sQh[64 * QSTR], sQl[64 * QSTR];
    __shared__ __nv_bfloat16 sKh[64 * QSTR], sKl[64 * QSTR];
    __shared__ __nv_bfloat16 sVh[32 * VSTR], sVl[32 * VSTR];
    __shared__ float bt[228];

    const int tid  = threadIdx.x;
    const int warp = tid >> 5;
    const int lane = tid & 31;

    const __nv_bfloat16* Qh = g_q_hi  + (size_t)bh * 2048;
    const __nv_bfloat16* Ql = g_q_lo  + (size_t)bh * 2048;
    const __nv_bfloat16* Kh = g_k_hi  + (size_t)bh * 2048;
    const __nv_bfloat16* Kl = g_k_lo  + (size_t)bh * 2048;
    const __nv_bfloat16* Vh = g_vt_hi + (size_t)bh * 2048;
    const __nv_bfloat16* Vl = g_vt_lo + (size_t)bh * 2048;

    for (int c = tid; c < 256; c += 128) {
        const int qr = c >> 2, qc = (c & 3) * 8;
        *(uint4*)(sQh + qr * QSTR + qc) = *(const uint4*)(Qh + c * 8);
        *(uint4*)(sQl + qr * QSTR + qc) = *(const uint4*)(Ql + c * 8);
        *(uint4*)(sKh + qr * QSTR + qc) = *(const uint4*)(Kh + c * 8);
        *(uint4*)(sKl + qr * QSTR + qc) = *(const uint4*)(Kl + c * 8);
        const int vr = c >> 3, vc = (c & 7) * 8;
        *(uint4*)(sVh + vr * VSTR + vc) = *(const uint4*)(Vh + c * 8);
        *(uint4*)(sVl + vr * VSTR + vc) = *(const uint4*)(Vl + c * 8);
    }
    for (int t = tid; t < 225; t += 128) bt[t] = bias_table[t * NHEADS + h];
    __syncthreads();

    const int gid = lane >> 2, tig = lane & 3;
    const int a_rowoff = (warp * 16 + (lane & 15)) * QSTR + (lane >> 4) * 8;
    const int b_row    = ((lane >> 4) << 3) + (lane & 7);
    const int b_ksel   = ((lane >> 3) & 1) << 3;

    // ---- QK^T ------------------------------------------------------------------
    float acc[8][4];
#pragma unroll
    for (int nt = 0; nt < 8; nt++)
#pragma unroll
        for (int c = 0; c < 4; c++) acc[nt][c] = 0.f;

#pragma unroll
    for (int kt = 0; kt < 2; kt++) {
        uint32_t qh[4], ql[4];
        ldsm_x4(qh, smem_u32(sQh + a_rowoff + kt * 16));
        ldsm_x4(ql, smem_u32(sQl + a_rowoff + kt * 16));
#pragma unroll
        for (int ng = 0; ng < 4; ng++) {
            uint32_t kh[4], kl[4];
            const int off = (ng * 16 + b_row) * QSTR + kt * 16 + b_ksel;
            ldsm_x4(kh, smem_u32(sKh + off));
            ldsm_x4(kl, smem_u32(sKl + off));
#pragma unroll
            for (int j = 0; j < 2; j++) {
                float* c = acc[ng * 2 + j];
                mma16816(c, qh, &kh[j * 2]);
                mma16816(c, qh, &kl[j * 2]);
                mma16816(c, ql, &kh[j * 2]);
            }
        }
    }

    // ---- bias + mask ----------------------------------------------------------
    const int i0 = warp * 16 + gid, i1 = i0 + 8;
    const int yi0 = i0 >> 3, xi0 = i0 & 7;
    const int yi1 = i1 >> 3, xi1 = i1 & 7;
    const float* mrow = mask + (size_t)b * 4096;
#pragma unroll
    for (int nt = 0; nt < 8; nt++) {
        const int col = nt * 8 + tig * 2;
        const float2 m0 = *(const float2*)(mrow + i0 * 64 + col);
        const float2 m1 = *(const float2*)(mrow + i1 * 64 + col);
        acc[nt][0] += bt[(yi0 - nt + 7) * 15 + (xi0 - tig * 2 + 7)] + m0.x;
        acc[nt][1] += bt[(yi0 - nt + 7) * 15 + (xi0 - tig * 2 + 6)] + m0.y;
        acc[nt][2] += bt[(yi1 - nt + 7) * 15 + (xi1 - tig * 2 + 7)] + m1.x;
        acc[nt][3] += bt[(yi1 - nt + 7) * 15 + (xi1 - tig * 2 + 6)] + m1.y;
    }

    // ---- softmax ---------------------------------------------------------------
    float mx0 = -1e30f, mx1 = -1e30f;
#pragma unroll
    for (int nt = 0; nt < 8; nt++) {
        mx0 = fmaxf(mx0, fmaxf(acc[nt][0], acc[nt][1]));
        mx1 = fmaxf(mx1, fmaxf(acc[nt][2], acc[nt][3]));
    }
    mx0 = fmaxf(mx0, __shfl_xor_sync(0xffffffffu, mx0, 1));
    mx0 = fmaxf(mx0, __shfl_xor_sync(0xffffffffu, mx0, 2));
    mx1 = fmaxf(mx1, __shfl_xor_sync(0xffffffffu, mx1, 1));
    mx1 = fmaxf(mx1, __shfl_xor_sync(0xffffffffu, mx1, 2));

    float sum0 = 0.f, sum1 = 0.f;
#pragma unroll
    for (int nt = 0; nt < 8; nt++) {
        acc[nt][0] = __expf(acc[nt][0] - mx0);
        acc[nt][1] = __expf(acc[nt][1] - mx0);
        acc[nt][2] = __expf(acc[nt][2] - mx1);
        acc[nt][3] = __expf(acc[nt][3] - mx1);
        sum0 += acc[nt][0] + acc[nt][1];
        sum1 += acc[nt][2] + acc[nt][3];
    }
    sum0 += __shfl_xor_sync(0xffffffffu, sum0, 1);
    sum0 += __shfl_xor_sync(0xffffffffu, sum0, 2);
    sum1 += __shfl_xor_sync(0xffffffffu, sum1, 1);
    sum1 += __shfl_xor_sync(0xffffffffu, sum1, 2);
    const float inv0 = 1.f / sum0, inv1 = 1.f / sum1;

    // ---- repack P into A-fragments (hi/lo split) --------------------------------
    uint32_t phi[4][4], plo[4][4];
#pragma unroll
    for (int kt = 0; kt < 4; kt++) {
        const float f[4][2] = {
            {acc[kt*2][0] * inv0,   acc[kt*2][1] * inv0},
            {acc[kt*2][2] * inv1,   acc[kt*2][3] * inv1},
            {acc[kt*2+1][0] * inv0, acc[kt*2+1][1] * inv0},
            {acc[kt*2+1][2] * inv1, acc[kt*2+1][3] * inv1}};
#pragma unroll
        for (int r = 0; r < 4; r++) {
            __nv_bfloat16 hx = __float2bfloat16(f[r][0]);
            __nv_bfloat16 hy = __float2bfloat16(f[r][1]);
            phi[kt][r] = pack_bf16x2(f[r][0], f[r][1]);
            plo[kt][r] = pack_bf16x2(f[r][0] - __bfloat162float(hx),
                                     f[r][1] - __bfloat162float(hy));
        }
    }

    // ---- P * V -------------------------------------------------------------------
    float ao[4][4];
#pragma unroll
    for (int dn = 0; dn < 4; dn++)
#pragma unroll
        for (int c = 0; c < 4; c++) ao[dn][c] = 0.f;

#pragma unroll
    for (int kt = 0; kt < 4; kt++) {
#pragma unroll
        for (int g = 0; g < 2; g++) {
            uint32_t vh[4], vl[4];
            const int off = (g * 16 + b_row) * VSTR + kt * 16 + b_ksel;
            ldsm_x4(vh, smem_u32(sVh + off));
            ldsm_x4(vl, smem_u32(sVl + off));
#pragma unroll
            for (int j = 0; j < 2; j++) {
                float* c = ao[g * 2 + j];
                mma16816(c, phi[kt], &vh[j * 2]);
                mma16816(c, phi[kt], &vl[j * 2]);
                mma16816(c, plo[kt], &vh[j * 2]);
            }
        }
    }

    // ---- epilogue: tf32-rounded fp32 for the proj GEMM --------------------------
#pragma unroll
    for (int dn = 0; dn < 4; dn++) {
        const int d = dn * 8 + tig * 2;
#pragma unroll
        for (int rs = 0; rs < 2; rs++) {
            const int row = rs ? i1 : i0;
            const float v0 = tf32r(ao[dn][rs * 2 + 0]);
            const float v1 = tf32r(ao[dn][rs * 2 + 1]);
            const size_t o = ((size_t)b * 64 + row) * DIM + h * 32 + d;
            *(float2*)(g_ao + o) = make_float2(v0, v1);
        }
    }
}

// ---------------- launch ----------------------------------------------------
extern "C" void kernel_launch(void* const* d_in, const int* in_sizes, int n_in,
                              void* d_out, int out_size)
{
    const float* x          = (const float*)d_in[0]; // (2048,64,256)
    const float* mask       = (const float*)d_in[1]; // (2048,1,64,64)
    const float* w_qkv      = (const float*)d_in[2]; // (768,256)
    const float* b_qkv      = (const float*)d_in[3]; // (768)
    const float* w_proj     = (const float*)d_in[4]; // (256,256)
    const float* b_proj     = (const float*)d_in[5]; // (256)
    const float* bias_table = (const float*)d_in[6]; // (225,8)
    float* out = (float*)d_out;                      // (2048,64,256)

    (void)in_sizes; (void)n_in; (void)out_size;

    float *ao, *wqr, *wpr;
    cudaGetSymbolAddress((void**)&ao,  g_ao);
    cudaGetSymbolAddress((void**)&wqr, g_wqr);
    cudaGetSymbolAddress((void**)&wpr, g_wpr);

    cudaFuncSetAttribute(gemm_tf32<0>, cudaFuncAttributeMaxDynamicSharedMemorySize, TGEMM_SMEM);
    cudaFuncSetAttribute(gemm_tf32<1>, cudaFuncAttributeMaxDynamicSharedMemorySize, TGEMM_SMEM);

    // 0) round weights to tf32 (x is rounded in-register inside the GEMM)
    {
        int w4 = (QKVDIM * DIM) / 4;
        round_tf32<<<(w4 + 255) / 256, 256>>>(w_qkv, wqr, w4);
        int p4 = (DIM * DIM) / 4;
        round_tf32<<<(p4 + 255) / 256, 256>>>(w_proj, wpr, p4);
    }
    // 1) QKV GEMM (tf32, occ=3 CTA/SM) -> q/k/vt bf16 hi/lo planes (q pre-scaled)
    {
        dim3 grid(QKVDIM / 64, MROWS / 128);   // 12 x 1024
        gemm_tf32<0><<<grid, 256, TGEMM_SMEM>>>(x, wqr, b_qkv, nullptr);
    }
    // 2) windowed attention (bf16 HMMA) -> g_ao (tf32-rounded fp32)
    attn_mma<<<B_WIN * NHEADS, 128>>>(mask, bias_table);
    // 3) output projection (tf32) -> out
    {
        dim3 grid(DIM / 64, MROWS / 128);      // 4 x 1024
        gemm_tf32<1><<<grid, 256, TGEMM_SMEM>>>(ao, wpr, b_proj, out);
    }
}

// round 13
// speedup vs baseline: 1.0278x; 1.0278x over previous
#include <cuda_runtime.h>
#include <cuda_bf16.h>
#include <cstdint>

#define B_WIN   2048
#define NTOK    64
#define DIM     256
#define NHEADS  8
#define QKVDIM  768
#define MROWS   (B_WIN * NTOK)          // 131072
#define SCALE   0.17677669529663687f    // 32^-0.5

// ---------------- scratch (device globals; no cudaMalloc allowed) ----------
#define HEAD_ELEMS (2048ull * 8ull * 64ull * 32ull)
__device__ __nv_bfloat16 g_q_hi[HEAD_ELEMS],  g_q_lo[HEAD_ELEMS];
__device__ __nv_bfloat16 g_k_hi[HEAD_ELEMS],  g_k_lo[HEAD_ELEMS];
__device__ __nv_bfloat16 g_vt_hi[HEAD_ELEMS], g_vt_lo[HEAD_ELEMS];  // [bh][d][n]
__device__ float g_ao[(size_t)MROWS * DIM];    // tf32-rounded attention out
__device__ float g_wqr[QKVDIM * DIM];          // tf32-rounded w_qkv
__device__ float g_wpr[DIM * DIM];             // tf32-rounded w_proj

// ================= helpers ==================================================
__device__ __forceinline__ uint32_t smem_u32(const void* p) {
    uint32_t a;
    asm("{ .reg .u64 t; cvta.to.shared.u64 t, %1; cvt.u32.u64 %0, t; }"
        : "=r"(a) : "l"(p));
    return a;
}

__device__ __forceinline__ void ldsm_x4(uint32_t* r, uint32_t addr) {
    asm volatile("ldmatrix.sync.aligned.m8n8.x4.shared.b16 {%0,%1,%2,%3}, [%4];"
                 : "=r"(r[0]), "=r"(r[1]), "=r"(r[2]), "=r"(r[3]) : "r"(addr));
}

// bf16 k16 mma (attention path)
__device__ __forceinline__ void mma16816(float* c, const uint32_t* a, const uint32_t* b) {
    asm volatile("mma.sync.aligned.m16n8k16.row.col.f32.bf16.bf16.f32 "
                 "{%0,%1,%2,%3}, {%4,%5,%6,%7}, {%8,%9}, {%0,%1,%2,%3};"
                 : "+f"(c[0]), "+f"(c[1]), "+f"(c[2]), "+f"(c[3])
                 : "r"(a[0]), "r"(a[1]), "r"(a[2]), "r"(a[3]),
                   "r"(b[0]), "r"(b[1]));
}

// tf32 k8 mma (GEMM path)
__device__ __forceinline__ void mma1688(float* c, const uint32_t* a,
                                        uint32_t b0, uint32_t b1) {
    asm volatile("mma.sync.aligned.m16n8k8.row.col.f32.tf32.tf32.f32 "
                 "{%0,%1,%2,%3}, {%4,%5,%6,%7}, {%8,%9}, {%0,%1,%2,%3};"
                 : "+f"(c[0]), "+f"(c[1]), "+f"(c[2]), "+f"(c[3])
                 : "r"(a[0]), "r"(a[1]), "r"(a[2]), "r"(a[3]),
                   "r"(b0), "r"(b1));
}

__device__ __forceinline__ float tf32r(float f) {
    uint32_t u;
    asm("cvt.rna.tf32.f32 %0, %1;" : "=r"(u) : "f"(f));
    return __uint_as_float(u);
}
__device__ __forceinline__ uint32_t tf32r_bits(uint32_t fb) {
    uint32_t u;
    asm("cvt.rna.tf32.f32 %0, %1;" : "=r"(u) : "f"(__uint_as_float(fb)));
    return u;
}

__device__ __forceinline__ uint32_t pack_bf16x2(float x, float y) {
    __nv_bfloat162 t = __floats2bfloat162_rn(x, y);
    return *(uint32_t*)&t;
}

__device__ __forceinline__ void cp16(uint32_t dst, const void* src) {
    asm volatile("cp.async.cg.shared.global [%0], [%1], 16;"
                 :: "r"(dst), "l"(src) : "memory");
}
#define CP_COMMIT() asm volatile("cp.async.commit_group;" ::: "memory")

// ================= fp32 -> tf32-rounded fp32 (weights only) ================
__global__ void round_tf32(const float* __restrict__ src,
                           float* __restrict__ dst, int n4)
{
    int i = blockIdx.x * blockDim.x + threadIdx.x;
    if (i >= n4) return;
    float4 v = ((const float4*)src)[i];
    v.x = tf32r(v.x); v.y = tf32r(v.y); v.z = tf32r(v.z); v.w = tf32r(v.w);
    ((float4*)dst)[i] = v;
}

// ================= TF32 GEMM (R11 config: 3-stage, 128x128, occ 2) ==========
#define TSTRW  36                   // fp32 words per smem row (144B, conflict-free)
#define T_A    0
#define T_B    18432                // 128*36*4
#define TSTAGE 36864
#define TGEMM_SMEM (3 * TSTAGE)     // 110592 bytes

template <int MODE>
__global__ void __launch_bounds__(256, 2)
gemm_tf32(const float* __restrict__ A, const float* __restrict__ W,
          const float* __restrict__ bias, float* __restrict__ out)
{
    extern __shared__ char smem[];
    const uint32_t sb = smem_u32(smem);

    const int tid  = threadIdx.x;
    const int lane = tid & 31;
    const int warp = tid >> 5;
    const int wm   = warp >> 1;          // 0..3
    const int wn   = warp & 1;           // 0..1
    const int row0 = blockIdx.y * 128;
    const int col0 = blockIdx.x * 128;

    float acc[2][8][4];
#pragma unroll
    for (int a = 0; a < 2; a++)
#pragma unroll
        for (int b = 0; b < 8; b++)
#pragma unroll
            for (int c = 0; c < 4; c++) acc[a][b][c] = 0.f;

    const int gid = lane >> 2, tig = lane & 3;

    auto issue = [&](int kc) {
        const uint32_t stb = sb + (kc % 3) * TSTAGE;
        const int k0 = kc * 32;
#pragma unroll
        for (int t = 0; t < 4; t++) {
            const int idx = tid + t * 256;
            const int r = idx >> 3, c8 = idx & 7;
            const uint32_t so = (uint32_t)r * 144 + c8 * 16;
            cp16(stb + T_A + so, A + (size_t)(row0 + r) * 256 + k0 + c8 * 4);
            cp16(stb + T_B + so, W + (size_t)(col0 + r) * 256 + k0 + c8 * 4);
        }
        CP_COMMIT();
    };

    issue(0);
    issue(1);

    const int lg = lane >> 3, lrw = lane & 7;
    const uint32_t a_ld = (uint32_t)((wm * 32 + ((lg & 1) << 3) + lrw) * TSTRW
                                     + ((lg >> 1) << 2)) * 4;
    const uint32_t b_ld = (uint32_t)((wn * 64 + ((lg >> 1) << 3) + lrw) * TSTRW
                                     + ((lg & 1) << 2)) * 4;

    for (int kc = 0; kc < 8; kc++) {
        if (kc < 7) {
            asm volatile("cp.async.wait_group 1;" ::: "memory");
        } else {
            asm volatile("cp.async.wait_group 0;" ::: "memory");
        }
        __syncthreads();                 // stage kc ready; stage (kc+2)%3 free
        if (kc + 2 < 8) issue(kc + 2);

        const uint32_t sA = sb + (kc % 3) * TSTAGE + T_A;
        const uint32_t sB = sb + (kc % 3) * TSTAGE + T_B;

#pragma unroll
        for (int ks = 0; ks < 4; ks++) {
            const uint32_t kso = (uint32_t)(ks * 8) * 4;
            uint32_t af[2][4], bf[4][4];
#pragma unroll
            for (int mt = 0; mt < 2; mt++) {
                ldsm_x4(af[mt], sA + a_ld + mt * 16 * TSTRW * 4 + kso);
#pragma unroll
                for (int i = 0; i < 4; i++)       // round raw fp32 A -> tf32
                    af[mt][i] = tf32r_bits(af[mt][i]);
            }
#pragma unroll
            for (int p = 0; p < 4; p++)
                ldsm_x4(bf[p], sB + b_ld + p * 16 * TSTRW * 4 + kso);
#pragma unroll
            for (int mt = 0; mt < 2; mt++)
#pragma unroll
                for (int nt = 0; nt < 8; nt++) {
                    const uint32_t* bb = &bf[nt >> 1][(nt & 1) * 2];
                    mma1688(acc[mt][nt], af[mt], bb[0], bb[1]);
                }
        }
    }

    // ---- epilogue -------------------------------------------------------------
#pragma unroll
    for (int mt = 0; mt < 2; mt++)
#pragma unroll
        for (int nt = 0; nt < 8; nt++) {
            const int col = col0 + wn * 64 + nt * 8 + tig * 2;
            const float2 bv = *(const float2*)(bias + col);
#pragma unroll
            for (int rs = 0; rs < 2; rs++) {
                const int row = row0 + wm * 32 + mt * 16 + gid + rs * 8;
                float v0 = acc[mt][nt][rs * 2 + 0] + bv.x;
                float v1 = acc[mt][nt][rs * 2 + 1] + bv.y;
                if (MODE == 0) {
                    const int s = col >> 8;
                    if (s == 0) { v0 *= SCALE; v1 *= SCALE; }
                    __nv_bfloat16 h0 = __float2bfloat16(v0);
                    __nv_bfloat16 l0 = __float2bfloat16(v0 - __bfloat162float(h0));
                    __nv_bfloat16 h1 = __float2bfloat16(v1);
                    __nv_bfloat16 l1 = __float2bfloat16(v1 - __bfloat162float(h1));
                    const int hh = (col >> 5) & 7, d = col & 31;
                    const int b = row >> 6, n = row & 63;
                    const size_t pb = (size_t)(b * 8 + hh) * 2048;
                    if (s == 0) {
                        *(__nv_bfloat162*)(g_q_hi + pb + n * 32 + d) = __halves2bfloat162(h0, h1);
                        *(__nv_bfloat162*)(g_q_lo + pb + n * 32 + d) = __halves2bfloat162(l0, l1);
                    } else if (s == 1) {
                        *(__nv_bfloat162*)(g_k_hi + pb + n * 32 + d) = __halves2bfloat162(h0, h1);
                        *(__nv_bfloat162*)(g_k_lo + pb + n * 32 + d) = __halves2bfloat162(l0, l1);
                    } else {   // v, stored transposed [d][n]
                        g_vt_hi[pb + (size_t)d * 64 + n]       = h0;
                        g_vt_hi[pb + (size_t)(d + 1) * 64 + n] = h1;
                        g_vt_lo[pb + (size_t)d * 64 + n]       = l0;
                        g_vt_lo[pb + (size_t)(d + 1) * 64 + n] = l1;
                    }
                } else {
                    *(float2*)(out + (size_t)row * 256 + col)
                        = make_float2(v0, v1);
                }
            }
        }
}

// ================= HMMA attention: one (window, head) per CTA ===============
// Register-deflated: P hi/lo fragments computed per-kt inside the PV loop
// (saves ~24 regs -> 6 CTAs/SM instead of 5).
#define QSTR 40
#define VSTR 72

__global__ void __launch_bounds__(128, 6)
attn_mma(const float* __restrict__ mask, const float* __restrict__ bias_table)
{
    const int bh = blockIdx.x;
    const int b  = bh >> 3;
    const int h  = bh & 7;

    __shared__ __nv_bfloat16 sQh[64 * QSTR], sQl[64 * QSTR];
    __shared__ __nv_bfloat16 sKh[64 * QSTR], sKl[64 * QSTR];
    __shared__ __nv_bfloat16 sVh[32 * VSTR], sVl[32 * VSTR];
    __shared__ float bt[228];

    const int tid  = threadIdx.x;
    const int warp = tid >> 5;
    const int lane = tid & 31;

    const __nv_bfloat16* Qh = g_q_hi  + (size_t)bh * 2048;
    const __nv_bfloat16* Ql = g_q_lo  + (size_t)bh * 2048;
    const __nv_bfloat16* Kh = g_k_hi  + (size_t)bh * 2048;
    const __nv_bfloat16* Kl = g_k_lo  + (size_t)bh * 2048;
    const __nv_bfloat16* Vh = g_vt_hi + (size_t)bh * 2048;
    const __nv_bfloat16* Vl = g_vt_lo + (size_t)bh * 2048;

    for (int c = tid; c < 256; c += 128) {
        const int qr = c >> 2, qc = (c & 3) * 8;
        *(uint4*)(sQh + qr * QSTR + qc) = *(const uint4*)(Qh + c * 8);
        *(uint4*)(sQl + qr * QSTR + qc) = *(const uint4*)(Ql + c * 8);
        *(uint4*)(sKh + qr * QSTR + qc) = *(const uint4*)(Kh + c * 8);
        *(uint4*)(sKl + qr * QSTR + qc) = *(const uint4*)(Kl + c * 8);
        const int vr = c >> 3, vc = (c & 7) * 8;
        *(uint4*)(sVh + vr * VSTR + vc) = *(const uint4*)(Vh + c * 8);
        *(uint4*)(sVl + vr * VSTR + vc) = *(const uint4*)(Vl + c * 8);
    }
    for (int t = tid; t < 225; t += 128) bt[t] = bias_table[t * NHEADS + h];
    __syncthreads();

    const int gid = lane >> 2, tig = lane & 3;
    const int a_rowoff = (warp * 16 + (lane & 15)) * QSTR + (lane >> 4) * 8;
    const int b_row    = ((lane >> 4) << 3) + (lane & 7);
    const int b_ksel   = ((lane >> 3) & 1) << 3;

    // ---- QK^T ------------------------------------------------------------------
    float acc[8][4];
#pragma unroll
    for (int nt = 0; nt < 8; nt++)
#pragma unroll
        for (int c = 0; c < 4; c++) acc[nt][c] = 0.f;

#pragma unroll
    for (int kt = 0; kt < 2; kt++) {
        uint32_t qh[4], ql[4];
        ldsm_x4(qh, smem_u32(sQh + a_rowoff + kt * 16));
        ldsm_x4(ql, smem_u32(sQl + a_rowoff + kt * 16));
#pragma unroll
        for (int ng = 0; ng < 4; ng++) {
            uint32_t kh[4], kl[4];
            const int off = (ng * 16 + b_row) * QSTR + kt * 16 + b_ksel;
            ldsm_x4(kh, smem_u32(sKh + off));
            ldsm_x4(kl, smem_u32(sKl + off));
#pragma unroll
            for (int j = 0; j < 2; j++) {
                float* c = acc[ng * 2 + j];
                mma16816(c, qh, &kh[j * 2]);
                mma16816(c, qh, &kl[j * 2]);
                mma16816(c, ql, &kh[j * 2]);
            }
        }
    }

    // ---- bias + mask ----------------------------------------------------------
    const int i0 = warp * 16 + gid, i1 = i0 + 8;
    const int yi0 = i0 >> 3, xi0 = i0 & 7;
    const int yi1 = i1 >> 3, xi1 = i1 & 7;
    const float* mrow = mask + (size_t)b * 4096;
#pragma unroll
    for (int nt = 0; nt < 8; nt++) {
        const int col = nt * 8 + tig * 2;
        const float2 m0 = *(const float2*)(mrow + i0 * 64 + col);
        const float2 m1 = *(const float2*)(mrow + i1 * 64 + col);
        acc[nt][0] += bt[(yi0 - nt + 7) * 15 + (xi0 - tig * 2 + 7)] + m0.x;
        acc[nt][1] += bt[(yi0 - nt + 7) * 15 + (xi0 - tig * 2 + 6)] + m0.y;
        acc[nt][2] += bt[(yi1 - nt + 7) * 15 + (xi1 - tig * 2 + 7)] + m1.x;
        acc[nt][3] += bt[(yi1 - nt + 7) * 15 + (xi1 - tig * 2 + 6)] + m1.y;
    }

    // ---- softmax ---------------------------------------------------------------
    float mx0 = -1e30f, mx1 = -1e30f;
#pragma unroll
    for (int nt = 0; nt < 8; nt++) {
        mx0 = fmaxf(mx0, fmaxf(acc[nt][0], acc[nt][1]));
        mx1 = fmaxf(mx1, fmaxf(acc[nt][2], acc[nt][3]));
    }
    mx0 = fmaxf(mx0, __shfl_xor_sync(0xffffffffu, mx0, 1));
    mx0 = fmaxf(mx0, __shfl_xor_sync(0xffffffffu, mx0, 2));
    mx1 = fmaxf(mx1, __shfl_xor_sync(0xffffffffu, mx1, 1));
    mx1 = fmaxf(mx1, __shfl_xor_sync(0xffffffffu, mx1, 2));

    float sum0 = 0.f, sum1 = 0.f;
#pragma unroll
    for (int nt = 0; nt < 8; nt++) {
        acc[nt][0] = __expf(acc[nt][0] - mx0);
        acc[nt][1] = __expf(acc[nt][1] - mx0);
        acc[nt][2] = __expf(acc[nt][2] - mx1);
        acc[nt][3] = __expf(acc[nt][3] - mx1);
        sum0 += acc[nt][0] + acc[nt][1];
        sum1 += acc[nt][2] + acc[nt][3];
    }
    sum0 += __shfl_xor_sync(0xffffffffu, sum0, 1);
    sum0 += __shfl_xor_sync(0xffffffffu, sum0, 2);
    sum1 += __shfl_xor_sync(0xffffffffu, sum1, 1);
    sum1 += __shfl_xor_sync(0xffffffffu, sum1, 2);
    const float inv0 = 1.f / sum0, inv1 = 1.f / sum1;

    // ---- P * V (P hi/lo fragments derived per-kt; low register footprint) -------
    float ao[4][4];
#pragma unroll
    for (int dn = 0; dn < 4; dn++)
#pragma unroll
        for (int c = 0; c < 4; c++) ao[dn][c] = 0.f;

#pragma unroll
    for (int kt = 0; kt < 4; kt++) {
        uint32_t phi[4], plo[4];
        {
            const float f[4][2] = {
                {acc[kt*2][0] * inv0,   acc[kt*2][1] * inv0},
                {acc[kt*2][2] * inv1,   acc[kt*2][3] * inv1},
                {acc[kt*2+1][0] * inv0, acc[kt*2+1][1] * inv0},
                {acc[kt*2+1][2] * inv1, acc[kt*2+1][3] * inv1}};
#pragma unroll
            for (int r = 0; r < 4; r++) {
                __nv_bfloat16 hx = __float2bfloat16(f[r][0]);
                __nv_bfloat16 hy = __float2bfloat16(f[r][1]);
                phi[r] = pack_bf16x2(f[r][0], f[r][1]);
                plo[r] = pack_bf16x2(f[r][0] - __bfloat162float(hx),
                                     f[r][1] - __bfloat162float(hy));
            }
        }
#pragma unroll
        for (int g = 0; g < 2; g++) {
            uint32_t vh[4], vl[4];
            const int off = (g * 16 + b_row) * VSTR + kt * 16 + b_ksel;
            ldsm_x4(vh, smem_u32(sVh + off));
            ldsm_x4(vl, smem_u32(sVl + off));
#pragma unroll
            for (int j = 0; j < 2; j++) {
                float* c = ao[g * 2 + j];
                mma16816(c, phi, &vh[j * 2]);
                mma16816(c, phi, &vl[j * 2]);
                mma16816(c, plo, &vh[j * 2]);
            }
        }
    }

    // ---- epilogue: tf32-rounded fp32 for the proj GEMM --------------------------
#pragma unroll
    for (int dn = 0; dn < 4; dn++) {
        const int d = dn * 8 + tig * 2;
#pragma unroll
        for (int rs = 0; rs < 2; rs++) {
            const int row = rs ? i1 : i0;
            const float v0 = tf32r(ao[dn][rs * 2 + 0]);
            const float v1 = tf32r(ao[dn][rs * 2 + 1]);
            const size_t o = ((size_t)b * 64 + row) * DIM + h * 32 + d;
            *(float2*)(g_ao + o) = make_float2(v0, v1);
        }
    }
}

// ---------------- launch ----------------------------------------------------
extern "C" void kernel_launch(void* const* d_in, const int* in_sizes, int n_in,
                              void* d_out, int out_size)
{
    const float* x          = (const float*)d_in[0]; // (2048,64,256)
    const float* mask       = (const float*)d_in[1]; // (2048,1,64,64)
    const float* w_qkv      = (const float*)d_in[2]; // (768,256)
    const float* b_qkv      = (const float*)d_in[3]; // (768)
    const float* w_proj     = (const float*)d_in[4]; // (256,256)
    const float* b_proj     = (const float*)d_in[5]; // (256)
    const float* bias_table = (const float*)d_in[6]; // (225,8)
    float* out = (float*)d_out;                      // (2048,64,256)

    (void)in_sizes; (void)n_in; (void)out_size;

    float *ao, *wqr, *wpr;
    cudaGetSymbolAddress((void**)&ao,  g_ao);
    cudaGetSymbolAddress((void**)&wqr, g_wqr);
    cudaGetSymbolAddress((void**)&wpr, g_wpr);

    cudaFuncSetAttribute(gemm_tf32<0>, cudaFuncAttributeMaxDynamicSharedMemorySize, TGEMM_SMEM);
    cudaFuncSetAttribute(gemm_tf32<1>, cudaFuncAttributeMaxDynamicSharedMemorySize, TGEMM_SMEM);

    // 0) round weights to tf32 (x is rounded in-register inside the GEMM)
    {
        int w4 = (QKVDIM * DIM) / 4;
        round_tf32<<<(w4 + 255) / 256, 256>>>(w_qkv, wqr, w4);
        int p4 = (DIM * DIM) / 4;
        round_tf32<<<(p4 + 255) / 256, 256>>>(w_proj, wpr, p4);
    }
    // 1) QKV GEMM (tf32, R11 config) -> q/k/vt bf16 hi/lo planes (q pre-scaled)
    {
        dim3 grid(QKVDIM / 128, MROWS / 128);   // 6 x 1024
        gemm_tf32<0><<<grid, 256, TGEMM_SMEM>>>(x, wqr, b_qkv, nullptr);
    }
    // 2) windowed attention (bf16 HMMA, occ-boosted) -> g_ao
    attn_mma<<<B_WIN * NHEADS, 128>>>(mask, bias_table);
    // 3) output projection (tf32) -> out
    {
        dim3 grid(DIM / 128, MROWS / 128);      // 2 x 1024
        gemm_tf32<1><<<grid, 256, TGEMM_SMEM>>>(ao, wpr, b_proj, out);
    }
}

// round 14
// speedup vs baseline: 1.3857x; 1.3482x over previous
#include <cuda_runtime.h>
#include <cuda_bf16.h>
#include <cuda_fp16.h>
#include <cstdint>

#define B_WIN   2048
#define NTOK    64
#define DIM     256
#define NHEADS  8
#define QKVDIM  768
#define MROWS   (B_WIN * NTOK)          // 131072
#define SCALE   0.17677669529663687f    // 32^-0.5

// ---------------- scratch (device globals; no cudaMalloc allowed) ----------
#define HEAD_ELEMS (2048ull * 8ull * 64ull * 32ull)
__device__ __nv_bfloat16 g_q_hi[HEAD_ELEMS],  g_q_lo[HEAD_ELEMS];
__device__ __nv_bfloat16 g_k_hi[HEAD_ELEMS],  g_k_lo[HEAD_ELEMS];
__device__ __nv_bfloat16 g_vt_hi[HEAD_ELEMS], g_vt_lo[HEAD_ELEMS];  // [bh][d][n]
__device__ __half g_xh[(size_t)MROWS * DIM];   // fp16 x
__device__ __half g_aoh[(size_t)MROWS * DIM];  // fp16 attention out
__device__ __half g_wqh[QKVDIM * DIM];         // fp16 w_qkv
__device__ __half g_wph[DIM * DIM];            // fp16 w_proj

// ================= helpers ==================================================
__device__ __forceinline__ uint32_t smem_u32(const void* p) {
    uint32_t a;
    asm("{ .reg .u64 t; cvta.to.shared.u64 t, %1; cvt.u32.u64 %0, t; }"
        : "=r"(a) : "l"(p));
    return a;
}

__device__ __forceinline__ void ldsm_x4(uint32_t* r, uint32_t addr) {
    asm volatile("ldmatrix.sync.aligned.m8n8.x4.shared.b16 {%0,%1,%2,%3}, [%4];"
                 : "=r"(r[0]), "=r"(r[1]), "=r"(r[2]), "=r"(r[3]) : "r"(addr));
}

// bf16 k16 mma (attention path)
__device__ __forceinline__ void mma16816(float* c, const uint32_t* a, const uint32_t* b) {
    asm volatile("mma.sync.aligned.m16n8k16.row.col.f32.bf16.bf16.f32 "
                 "{%0,%1,%2,%3}, {%4,%5,%6,%7}, {%8,%9}, {%0,%1,%2,%3};"
                 : "+f"(c[0]), "+f"(c[1]), "+f"(c[2]), "+f"(c[3])
                 : "r"(a[0]), "r"(a[1]), "r"(a[2]), "r"(a[3]),
                   "r"(b[0]), "r"(b[1]));
}

// fp16 k16 mma, fp32 accumulate (GEMM path)
__device__ __forceinline__ void mma16816h(float* c, const uint32_t* a, const uint32_t* b) {
    asm volatile("mma.sync.aligned.m16n8k16.row.col.f32.f16.f16.f32 "
                 "{%0,%1,%2,%3}, {%4,%5,%6,%7}, {%8,%9}, {%0,%1,%2,%3};"
                 : "+f"(c[0]), "+f"(c[1]), "+f"(c[2]), "+f"(c[3])
                 : "r"(a[0]), "r"(a[1]), "r"(a[2]), "r"(a[3]),
                   "r"(b[0]), "r"(b[1]));
}

__device__ __forceinline__ uint32_t pack_bf16x2(float x, float y) {
    __nv_bfloat162 t = __floats2bfloat162_rn(x, y);
    return *(uint32_t*)&t;
}

__device__ __forceinline__ void cp16(uint32_t dst, const void* src) {
    asm volatile("cp.async.cg.shared.global [%0], [%1], 16;"
                 :: "r"(dst), "l"(src) : "memory");
}
#define CP_COMMIT() asm volatile("cp.async.commit_group;" ::: "memory")

// ================= fp32 -> fp16 convert =====================================
__global__ void convert_half(const float* __restrict__ src,
                             __half* __restrict__ dst, int n4)
{
    int i = blockIdx.x * blockDim.x + threadIdx.x;
    if (i >= n4) return;
    float4 v = ((const float4*)src)[i];
    __half2 a = __floats2half2_rn(v.x, v.y);
    __half2 b = __floats2half2_rn(v.z, v.w);
    ((__half2*)dst)[2*i]   = a;
    ((__half2*)dst)[2*i+1] = b;
}

// ================= FP16 GEMM (3-stage cp.async, single-pass) ================
// C[128 x 128] = A[128 x 256] * W[128 x 256]^T, fp16 in, fp32 acc.
// 8 warps 4(M)x2(N), warp tile 32x64, BK=32, 3 stages, 1 barrier/chunk.
// Fragment layout identical to the R6/R7 verified bf16 path (ldsm b16).
// MODE 0: epilogue splits into q/k/vt bf16 hi/lo planes (q scaled).
// MODE 1: writes fp32 `out`.

#define HSTR   40                   // halves per smem row (80B, conflict-free)
#define HROWB  80
#define H_A    0
#define H_B    10240                // 128*80
#define HSTAGE 20480
#define HGEMM_SMEM (3 * HSTAGE)     // 61440 bytes

template <int MODE>
__global__ void __launch_bounds__(256, 2)
gemm_fp16(const __half* __restrict__ A, const __half* __restrict__ W,
          const float* __restrict__ bias, float* __restrict__ out)
{
    extern __shared__ char smem[];
    const uint32_t sb = smem_u32(smem);

    const int tid  = threadIdx.x;
    const int lane = tid & 31;
    const int warp = tid >> 5;
    const int wm   = warp >> 1;          // 0..3
    const int wn   = warp & 1;           // 0..1
    const int row0 = blockIdx.y * 128;
    const int col0 = blockIdx.x * 128;

    float acc[2][8][4];
#pragma unroll
    for (int a = 0; a < 2; a++)
#pragma unroll
        for (int b = 0; b < 8; b++)
#pragma unroll
            for (int c = 0; c < 4; c++) acc[a][b][c] = 0.f;

    const int gid = lane >> 2, tig = lane & 3;

    // per-thread load geometry: 512 16B chunks per plane per stage (2/thread)
    const int lr  = tid >> 2;            // rows 0..63 (+64 on t=1)
    const int lc8 = (tid & 3) * 8;       // half col 0,8,16,24
    const uint32_t so_base = (uint32_t)lr * HROWB + (tid & 3) * 16;

    auto issue = [&](int kc) {
        const uint32_t stb = sb + (kc % 3) * HSTAGE;
        const int k0 = kc * 32;
#pragma unroll
        for (int t = 0; t < 2; t++) {
            const int r = lr + t * 64;
            const uint32_t so = so_base + t * 64 * HROWB;
            cp16(stb + H_A + so, A + (size_t)(row0 + r) * 256 + k0 + lc8);
            cp16(stb + H_B + so, W + (size_t)(col0 + r) * 256 + k0 + lc8);
        }
        CP_COMMIT();
    };

    issue(0);
    issue(1);

    // ldsm lane addressing (R6-verified bf16/fp16 k16 layout, HSTR=40)
    const int a_row  = wm * 32 + (lane & 15);
    const int a_ksel = (lane >> 4) * 8;
    const int b_rowb = wn * 64 + ((lane >> 4) << 3) + (lane & 7);
    const int b_ksel = ((lane >> 3) & 1) << 3;

    for (int kc = 0; kc < 8; kc++) {
        if (kc < 7) {
            asm volatile("cp.async.wait_group 1;" ::: "memory");
        } else {
            asm volatile("cp.async.wait_group 0;" ::: "memory");
        }
        __syncthreads();                 // stage kc ready; stage (kc+2)%3 free
        if (kc + 2 < 8) issue(kc + 2);

        const uint32_t sA = sb + (kc % 3) * HSTAGE + H_A;
        const uint32_t sB = sb + (kc % 3) * HSTAGE + H_B;

#pragma unroll
        for (int kk = 0; kk < 32; kk += 16) {
            uint32_t af[2][4];
#pragma unroll
            for (int mt = 0; mt < 2; mt++)
                ldsm_x4(af[mt], sA + (uint32_t)(a_row + mt * 16) * HROWB
                                   + (kk + a_ksel) * 2);
#pragma unroll
            for (int g = 0; g < 4; g++) {
                uint32_t bf[4];
                ldsm_x4(bf, sB + (uint32_t)(b_rowb + g * 16) * HROWB
                               + (kk + b_ksel) * 2);
#pragma unroll
                for (int mt = 0; mt < 2; mt++)
#pragma unroll
                    for (int j = 0; j < 2; j++)
                        mma16816h(acc[mt][g * 2 + j], af[mt], &bf[j * 2]);
            }
        }
    }

    // ---- epilogue -------------------------------------------------------------
#pragma unroll
    for (int mt = 0; mt < 2; mt++)
#pragma unroll
        for (int g = 0; g < 4; g++)
#pragma unroll
            for (int j = 0; j < 2; j++) {
                const int nf = g * 2 + j;
                const int col = col0 + wn * 64 + g * 16 + j * 8 + tig * 2;
                const float2 bv = *(const float2*)(bias + col);
#pragma unroll
                for (int rs = 0; rs < 2; rs++) {
                    const int row = row0 + wm * 32 + mt * 16 + gid + rs * 8;
                    float v0 = acc[mt][nf][rs * 2 + 0] + bv.x;
                    float v1 = acc[mt][nf][rs * 2 + 1] + bv.y;
                    if (MODE == 0) {
                        const int s = col >> 8;
                        if (s == 0) { v0 *= SCALE; v1 *= SCALE; }
                        __nv_bfloat16 h0 = __float2bfloat16(v0);
                        __nv_bfloat16 l0 = __float2bfloat16(v0 - __bfloat162float(h0));
                        __nv_bfloat16 h1 = __float2bfloat16(v1);
                        __nv_bfloat16 l1 = __float2bfloat16(v1 - __bfloat162float(h1));
                        const int hh = (col >> 5) & 7, d = col & 31;
                        const int b = row >> 6, n = row & 63;
                        const size_t pb = (size_t)(b * 8 + hh) * 2048;
                        if (s == 0) {
                            *(__nv_bfloat162*)(g_q_hi + pb + n * 32 + d) = __halves2bfloat162(h0, h1);
                            *(__nv_bfloat162*)(g_q_lo + pb + n * 32 + d) = __halves2bfloat162(l0, l1);
                        } else if (s == 1) {
                            *(__nv_bfloat162*)(g_k_hi + pb + n * 32 + d) = __halves2bfloat162(h0, h1);
                            *(__nv_bfloat162*)(g_k_lo + pb + n * 32 + d) = __halves2bfloat162(l0, l1);
                        } else {   // v, stored transposed [d][n]
                            g_vt_hi[pb + (size_t)d * 64 + n]       = h0;
                            g_vt_hi[pb + (size_t)(d + 1) * 64 + n] = h1;
                            g_vt_lo[pb + (size_t)d * 64 + n]       = l0;
                            g_vt_lo[pb + (size_t)(d + 1) * 64 + n] = l1;
                        }
                    } else {
                        *(float2*)(out + (size_t)row * 256 + col)
                            = make_float2(v0, v1);
                    }
                }
            }
}

// ================= HMMA attention: one (window, head) per CTA ===============
#define QSTR 40
#define VSTR 72

__global__ void __launch_bounds__(128)
attn_mma(const float* __restrict__ mask, const float* __restrict__ bias_table)
{
    const int bh = blockIdx.x;
    const int b  = bh >> 3;
    const int h  = bh & 7;

    __shared__ __nv_bfloat16 sQh[64 * QSTR], sQl[64 * QSTR];
    __shared__ __nv_bfloat16 sKh[64 * QSTR], sKl[64 * QSTR];
    __shared__ __nv_bfloat16 sVh[32 * VSTR], sVl[32 * VSTR];
    __shared__ float bt[228];

    const int tid  = threadIdx.x;
    const int warp = tid >> 5;
    const int lane = tid & 31;

    const __nv_bfloat16* Qh = g_q_hi  + (size_t)bh * 2048;
    const __nv_bfloat16* Ql = g_q_lo  + (size_t)bh * 2048;
    const __nv_bfloat16* Kh = g_k_hi  + (size_t)bh * 2048;
    const __nv_bfloat16* Kl = g_k_lo  + (size_t)bh * 2048;
    const __nv_bfloat16* Vh = g_vt_hi + (size_t)bh * 2048;
    const __nv_bfloat16* Vl = g_vt_lo + (size_t)bh * 2048;

    for (int c = tid; c < 256; c += 128) {
        const int qr = c >> 2, qc = (c & 3) * 8;
        *(uint4*)(sQh + qr * QSTR + qc) = *(const uint4*)(Qh + c * 8);
        *(uint4*)(sQl + qr * QSTR + qc) = *(const uint4*)(Ql + c * 8);
        *(uint4*)(sKh + qr * QSTR + qc) = *(const uint4*)(Kh + c * 8);
        *(uint4*)(sKl + qr * QSTR + qc) = *(const uint4*)(Kl + c * 8);
        const int vr = c >> 3, vc = (c & 7) * 8;
        *(uint4*)(sVh + vr * VSTR + vc) = *(const uint4*)(Vh + c * 8);
        *(uint4*)(sVl + vr * VSTR + vc) = *(const uint4*)(Vl + c * 8);
    }
    for (int t = tid; t < 225; t += 128) bt[t] = bias_table[t * NHEADS + h];
    __syncthreads();

    const int gid = lane >> 2, tig = lane & 3;
    const int a_rowoff = (warp * 16 + (lane & 15)) * QSTR + (lane >> 4) * 8;
    const int b_row    = ((lane >> 4) << 3) + (lane & 7);
    const int b_ksel   = ((lane >> 3) & 1) << 3;

    // ---- QK^T ------------------------------------------------------------------
    float acc[8][4];
#pragma unroll
    for (int nt = 0; nt < 8; nt++)
#pragma unroll
        for (int c = 0; c < 4; c++) acc[nt][c] = 0.f;

#pragma unroll
    for (int kt = 0; kt < 2; kt++) {
        uint32_t qh[4], ql[4];
        ldsm_x4(qh, smem_u32(sQh + a_rowoff + kt * 16));
        ldsm_x4(ql, smem_u32(sQl + a_rowoff + kt * 16));
#pragma unroll
        for (int ng = 0; ng < 4; ng++) {
            uint32_t kh[4], kl[4];
            const int off = (ng * 16 + b_row) * QSTR + kt * 16 + b_ksel;
            ldsm_x4(kh, smem_u32(sKh + off));
            ldsm_x4(kl, smem_u32(sKl + off));
#pragma unroll
            for (int j = 0; j < 2; j++) {
                float* c = acc[ng * 2 + j];
                mma16816(c, qh, &kh[j * 2]);
                mma16816(c, qh, &kl[j * 2]);
                mma16816(c, ql, &kh[j * 2]);
            }
        }
    }

    // ---- bias + mask ----------------------------------------------------------
    const int i0 = warp * 16 + gid, i1 = i0 + 8;
    const int yi0 = i0 >> 3, xi0 = i0 & 7;
    const int yi1 = i1 >> 3, xi1 = i1 & 7;
    const float* mrow = mask + (size_t)b * 4096;
#pragma unroll
    for (int nt = 0; nt < 8; nt++) {
        const int col = nt * 8 + tig * 2;
        const float2 m0 = *(const float2*)(mrow + i0 * 64 + col);
        const float2 m1 = *(const float2*)(mrow + i1 * 64 + col);
        acc[nt][0] += bt[(yi0 - nt + 7) * 15 + (xi0 - tig * 2 + 7)] + m0.x;
        acc[nt][1] += bt[(yi0 - nt + 7) * 15 + (xi0 - tig * 2 + 6)] + m0.y;
        acc[nt][2] += bt[(yi1 - nt + 7) * 15 + (xi1 - tig * 2 + 7)] + m1.x;
        acc[nt][3] += bt[(yi1 - nt + 7) * 15 + (xi1 - tig * 2 + 6)] + m1.y;
    }

    // ---- softmax ---------------------------------------------------------------
    float mx0 = -1e30f, mx1 = -1e30f;
#pragma unroll
    for (int nt = 0; nt < 8; nt++) {
        mx0 = fmaxf(mx0, fmaxf(acc[nt][0], acc[nt][1]));
        mx1 = fmaxf(mx1, fmaxf(acc[nt][2], acc[nt][3]));
    }
    mx0 = fmaxf(mx0, __shfl_xor_sync(0xffffffffu, mx0, 1));
    mx0 = fmaxf(mx0, __shfl_xor_sync(0xffffffffu, mx0, 2));
    mx1 = fmaxf(mx1, __shfl_xor_sync(0xffffffffu, mx1, 1));
    mx1 = fmaxf(mx1, __shfl_xor_sync(0xffffffffu, mx1, 2));

    float sum0 = 0.f, sum1 = 0.f;
#pragma unroll
    for (int nt = 0; nt < 8; nt++) {
        acc[nt][0] = __expf(acc[nt][0] - mx0);
        acc[nt][1] = __expf(acc[nt][1] - mx0);
        acc[nt][2] = __expf(acc[nt][2] - mx1);
        acc[nt][3] = __expf(acc[nt][3] - mx1);
        sum0 += acc[nt][0] + acc[nt][1];
        sum1 += acc[nt][2] + acc[nt][3];
    }
    sum0 += __shfl_xor_sync(0xffffffffu, sum0, 1);
    sum0 += __shfl_xor_sync(0xffffffffu, sum0, 2);
    sum1 += __shfl_xor_sync(0xffffffffu, sum1, 1);
    sum1 += __shfl_xor_sync(0xffffffffu, sum1, 2);
    const float inv0 = 1.f / sum0, inv1 = 1.f / sum1;

    // ---- repack P into A-fragments (hi/lo split) --------------------------------
    uint32_t phi[4][4], plo[4][4];
#pragma unroll
    for (int kt = 0; kt < 4; kt++) {
        const float f[4][2] = {
            {acc[kt*2][0] * inv0,   acc[kt*2][1] * inv0},
            {acc[kt*2][2] * inv1,   acc[kt*2][3] * inv1},
            {acc[kt*2+1][0] * inv0, acc[kt*2+1][1] * inv0},
            {acc[kt*2+1][2] * inv1, acc[kt*2+1][3] * inv1}};
#pragma unroll
        for (int r = 0; r < 4; r++) {
            __nv_bfloat16 hx = __float2bfloat16(f[r][0]);
            __nv_bfloat16 hy = __float2bfloat16(f[r][1]);
            phi[kt][r] = pack_bf16x2(f[r][0], f[r][1]);
            plo[kt][r] = pack_bf16x2(f[r][0] - __bfloat162float(hx),
                                     f[r][1] - __bfloat162float(hy));
        }
    }

    // ---- P * V -------------------------------------------------------------------
    float ao[4][4];
#pragma unroll
    for (int dn = 0; dn < 4; dn++)
#pragma unroll
        for (int c = 0; c < 4; c++) ao[dn][c] = 0.f;

#pragma unroll
    for (int kt = 0; kt < 4; kt++) {
#pragma unroll
        for (int g = 0; g < 2; g++) {
            uint32_t vh[4], vl[4];
            const int off = (g * 16 + b_row) * VSTR + kt * 16 + b_ksel;
            ldsm_x4(vh, smem_u32(sVh + off));
            ldsm_x4(vl, smem_u32(sVl + off));
#pragma unroll
            for (int j = 0; j < 2; j++) {
                float* c = ao[g * 2 + j];
                mma16816(c, phi[kt], &vh[j * 2]);
                mma16816(c, phi[kt], &vl[j * 2]);
                mma16816(c, plo[kt], &vh[j * 2]);
            }
        }
    }

    // ---- epilogue: fp16 ao plane for the fp16 proj GEMM -------------------------
#pragma unroll
    for (int dn = 0; dn < 4; dn++) {
        const int d = dn * 8 + tig * 2;
#pragma unroll
        for (int rs = 0; rs < 2; rs++) {
            const int row = rs ? i1 : i0;
            const size_t o = ((size_t)b * 64 + row) * DIM + h * 32 + d;
            *(__half2*)(g_aoh + o) =
                __floats2half2_rn(ao[dn][rs * 2 + 0], ao[dn][rs * 2 + 1]);
        }
    }
}

// ---------------- launch ----------------------------------------------------
extern "C" void kernel_launch(void* const* d_in, const int* in_sizes, int n_in,
                              void* d_out, int out_size)
{
    const float* x          = (const float*)d_in[0]; // (2048,64,256)
    const float* mask       = (const float*)d_in[1]; // (2048,1,64,64)
    const float* w_qkv      = (const float*)d_in[2]; // (768,256)
    const float* b_qkv      = (const float*)d_in[3]; // (768)
    const float* w_proj     = (const float*)d_in[4]; // (256,256)
    const float* b_proj     = (const float*)d_in[5]; // (256)
    const float* bias_table = (const float*)d_in[6]; // (225,8)
    float* out = (float*)d_out;                      // (2048,64,256)

    (void)in_sizes; (void)n_in; (void)out_size;

    __half *xh, *aoh, *wqh, *wph;
    cudaGetSymbolAddress((void**)&xh,  g_xh);
    cudaGetSymbolAddress((void**)&aoh, g_aoh);
    cudaGetSymbolAddress((void**)&wqh, g_wqh);
    cudaGetSymbolAddress((void**)&wph, g_wph);

    cudaFuncSetAttribute(gemm_fp16<0>, cudaFuncAttributeMaxDynamicSharedMemorySize, HGEMM_SMEM);
    cudaFuncSetAttribute(gemm_fp16<1>, cudaFuncAttributeMaxDynamicSharedMemorySize, HGEMM_SMEM);

    // 0) fp32 -> fp16 converts
    {
        int n4 = (MROWS * DIM) / 4;
        convert_half<<<(n4 + 255) / 256, 256>>>(x, xh, n4);
        int w4 = (QKVDIM * DIM) / 4;
        convert_half<<<(w4 + 255) / 256, 256>>>(w_qkv, wqh, w4);
        int p4 = (DIM * DIM) / 4;
        convert_half<<<(p4 + 255) / 256, 256>>>(w_proj, wph, p4);
    }
    // 1) QKV GEMM (fp16 single-pass) -> q/k/vt bf16 hi/lo planes (q pre-scaled)
    {
        dim3 grid(QKVDIM / 128, MROWS / 128);   // 6 x 1024
        gemm_fp16<0><<<grid, 256, HGEMM_SMEM>>>(xh, wqh, b_qkv, nullptr);
    }
    // 2) windowed attention (bf16 HMMA 3-term) -> g_aoh (fp16)
    attn_mma<<<B_WIN * NHEADS, 128>>>(mask, bias_table);
    // 3) output projection (fp16 single-pass) -> out
    {
        dim3 grid(DIM / 128, MROWS / 128);      // 2 x 1024
        gemm_fp16<1><<<grid, 256, HGEMM_SMEM>>>(aoh, wph, b_proj, out);
    }
}

// round 15
// speedup vs baseline: 1.6605x; 1.1983x over previous
#include <cuda_runtime.h>
#include <cuda_bf16.h>
#include <cuda_fp16.h>
#include <cstdint>

#define B_WIN   2048
#define NTOK    64
#define DIM     256
#define NHEADS  8
#define QKVDIM  768
#define MROWS   (B_WIN * NTOK)          // 131072
#define SCALE   0.17677669529663687f    // 32^-0.5

// ---------------- scratch (device globals; no cudaMalloc allowed) ----------
#define HEAD_ELEMS (2048ull * 8ull * 64ull * 32ull)
__device__ __half g_qh[HEAD_ELEMS];            // fp16 q (scaled), [bh][n][d]
__device__ __half g_kh[HEAD_ELEMS];            // fp16 k,          [bh][n][d]
__device__ __half g_vth[HEAD_ELEMS];           // fp16 v^T,        [bh][d][n]
__device__ __half g_xh[(size_t)MROWS * DIM];   // fp16 x
__device__ __half g_aoh[(size_t)MROWS * DIM];  // fp16 attention out
__device__ __half g_wqh[QKVDIM * DIM];         // fp16 w_qkv
__device__ __half g_wph[DIM * DIM];            // fp16 w_proj

// ================= helpers ==================================================
__device__ __forceinline__ uint32_t smem_u32(const void* p) {
    uint32_t a;
    asm("{ .reg .u64 t; cvta.to.shared.u64 t, %1; cvt.u32.u64 %0, t; }"
        : "=r"(a) : "l"(p));
    return a;
}

__device__ __forceinline__ void ldsm_x4(uint32_t* r, uint32_t addr) {
    asm volatile("ldmatrix.sync.aligned.m8n8.x4.shared.b16 {%0,%1,%2,%3}, [%4];"
                 : "=r"(r[0]), "=r"(r[1]), "=r"(r[2]), "=r"(r[3]) : "r"(addr));
}

// fp16 k16 mma, fp32 accumulate
__device__ __forceinline__ void mma16816h(float* c, const uint32_t* a, const uint32_t* b) {
    asm volatile("mma.sync.aligned.m16n8k16.row.col.f32.f16.f16.f32 "
                 "{%0,%1,%2,%3}, {%4,%5,%6,%7}, {%8,%9}, {%0,%1,%2,%3};"
                 : "+f"(c[0]), "+f"(c[1]), "+f"(c[2]), "+f"(c[3])
                 : "r"(a[0]), "r"(a[1]), "r"(a[2]), "r"(a[3]),
                   "r"(b[0]), "r"(b[1]));
}

__device__ __forceinline__ uint32_t pack_half2(float x, float y) {
    __half2 t = __floats2half2_rn(x, y);
    return *(uint32_t*)&t;
}

__device__ __forceinline__ void cp16(uint32_t dst, const void* src) {
    asm volatile("cp.async.cg.shared.global [%0], [%1], 16;"
                 :: "r"(dst), "l"(src) : "memory");
}
#define CP_COMMIT() asm volatile("cp.async.commit_group;" ::: "memory")

// ================= fp32 -> fp16 convert =====================================
__global__ void convert_half(const float* __restrict__ src,
                             __half* __restrict__ dst, int n4)
{
    int i = blockIdx.x * blockDim.x + threadIdx.x;
    if (i >= n4) return;
    float4 v = ((const float4*)src)[i];
    ((__half2*)dst)[2*i]   = __floats2half2_rn(v.x, v.y);
    ((__half2*)dst)[2*i+1] = __floats2half2_rn(v.z, v.w);
}

// ================= FP16 GEMM (3-stage cp.async, single-pass) ================
// C[128 x 128] = A[128 x 256] * W[128 x 256]^T, fp16 in, fp32 acc.
// 8 warps 4(M)x2(N), warp tile 32x64, BK=32, 3 stages, 1 barrier/chunk.
// MODE 0: epilogue writes q (scaled) / k / vt single fp16 planes.
// MODE 1: writes fp32 `out`.

#define HSTR   40                   // halves per smem row (80B, conflict-free)
#define HROWB  80
#define H_A    0
#define H_B    10240                // 128*80
#define HSTAGE 20480
#define HGEMM_SMEM (3 * HSTAGE)     // 61440 bytes

template <int MODE>
__global__ void __launch_bounds__(256, 2)
gemm_fp16(const __half* __restrict__ A, const __half* __restrict__ W,
          const float* __restrict__ bias, float* __restrict__ out)
{
    extern __shared__ char smem[];
    const uint32_t sb = smem_u32(smem);

    const int tid  = threadIdx.x;
    const int lane = tid & 31;
    const int warp = tid >> 5;
    const int wm   = warp >> 1;          // 0..3
    const int wn   = warp & 1;           // 0..1
    const int row0 = blockIdx.y * 128;
    const int col0 = blockIdx.x * 128;

    float acc[2][8][4];
#pragma unroll
    for (int a = 0; a < 2; a++)
#pragma unroll
        for (int b = 0; b < 8; b++)
#pragma unroll
            for (int c = 0; c < 4; c++) acc[a][b][c] = 0.f;

    const int gid = lane >> 2, tig = lane & 3;

    const int lr  = tid >> 2;
    const int lc8 = (tid & 3) * 8;
    const uint32_t so_base = (uint32_t)lr * HROWB + (tid & 3) * 16;

    auto issue = [&](int kc) {
        const uint32_t stb = sb + (kc % 3) * HSTAGE;
        const int k0 = kc * 32;
#pragma unroll
        for (int t = 0; t < 2; t++) {
            const int r = lr + t * 64;
            const uint32_t so = so_base + t * 64 * HROWB;
            cp16(stb + H_A + so, A + (size_t)(row0 + r) * 256 + k0 + lc8);
            cp16(stb + H_B + so, W + (size_t)(col0 + r) * 256 + k0 + lc8);
        }
        CP_COMMIT();
    };

    issue(0);
    issue(1);

    const int a_row  = wm * 32 + (lane & 15);
    const int a_ksel = (lane >> 4) * 8;
    const int b_rowb = wn * 64 + ((lane >> 4) << 3) + (lane & 7);
    const int b_ksel = ((lane >> 3) & 1) << 3;

    for (int kc = 0; kc < 8; kc++) {
        if (kc < 7) {
            asm volatile("cp.async.wait_group 1;" ::: "memory");
        } else {
            asm volatile("cp.async.wait_group 0;" ::: "memory");
        }
        __syncthreads();
        if (kc + 2 < 8) issue(kc + 2);

        const uint32_t sA = sb + (kc % 3) * HSTAGE + H_A;
        const uint32_t sB = sb + (kc % 3) * HSTAGE + H_B;

#pragma unroll
        for (int kk = 0; kk < 32; kk += 16) {
            uint32_t af[2][4];
#pragma unroll
            for (int mt = 0; mt < 2; mt++)
                ldsm_x4(af[mt], sA + (uint32_t)(a_row + mt * 16) * HROWB
                                   + (kk + a_ksel) * 2);
#pragma unroll
            for (int g = 0; g < 4; g++) {
                uint32_t bf[4];
                ldsm_x4(bf, sB + (uint32_t)(b_rowb + g * 16) * HROWB
                               + (kk + b_ksel) * 2);
#pragma unroll
                for (int mt = 0; mt < 2; mt++)
#pragma unroll
                    for (int j = 0; j < 2; j++)
                        mma16816h(acc[mt][g * 2 + j], af[mt], &bf[j * 2]);
            }
        }
    }

    // ---- epilogue -------------------------------------------------------------
#pragma unroll
    for (int mt = 0; mt < 2; mt++)
#pragma unroll
        for (int g = 0; g < 4; g++)
#pragma unroll
            for (int j = 0; j < 2; j++) {
                const int nf = g * 2 + j;
                const int col = col0 + wn * 64 + g * 16 + j * 8 + tig * 2;
                const float2 bv = *(const float2*)(bias + col);
#pragma unroll
                for (int rs = 0; rs < 2; rs++) {
                    const int row = row0 + wm * 32 + mt * 16 + gid + rs * 8;
                    float v0 = acc[mt][nf][rs * 2 + 0] + bv.x;
                    float v1 = acc[mt][nf][rs * 2 + 1] + bv.y;
                    if (MODE == 0) {
                        const int s = col >> 8;
                        if (s == 0) { v0 *= SCALE; v1 *= SCALE; }
                        const int hh = (col >> 5) & 7, d = col & 31;
                        const int b = row >> 6, n = row & 63;
                        const size_t pb = (size_t)(b * 8 + hh) * 2048;
                        if (s == 0) {
                            *(__half2*)(g_qh + pb + n * 32 + d) =
                                __floats2half2_rn(v0, v1);
                        } else if (s == 1) {
                            *(__half2*)(g_kh + pb + n * 32 + d) =
                                __floats2half2_rn(v0, v1);
                        } else {   // v, stored transposed [d][n]
                            g_vth[pb + (size_t)d * 64 + n]       = __float2half_rn(v0);
                            g_vth[pb + (size_t)(d + 1) * 64 + n] = __float2half_rn(v1);
                        }
                    } else {
                        *(float2*)(out + (size_t)row * 256 + col)
                            = make_float2(v0, v1);
                    }
                }
            }
}

// ================= fp16 attention: one (window, head) per CTA ===============
// Single-pass fp16 QK and PV (inputs already carry ~2^-11 error from the
// fp16 QKV GEMM; extra precision was wasted). 16+16 mma per warp.
#define QSTR 40
#define VSTR 72

__global__ void __launch_bounds__(128)
attn_mma(const float* __restrict__ mask, const float* __restrict__ bias_table)
{
    const int bh = blockIdx.x;
    const int b  = bh >> 3;
    const int h  = bh & 7;

    __shared__ __half sQ[64 * QSTR];
    __shared__ __half sK[64 * QSTR];
    __shared__ __half sV[32 * VSTR];
    __shared__ float bt[228];

    const int tid  = threadIdx.x;
    const int warp = tid >> 5;
    const int lane = tid & 31;

    const __half* Qp = g_qh  + (size_t)bh * 2048;
    const __half* Kp = g_kh  + (size_t)bh * 2048;
    const __half* Vp = g_vth + (size_t)bh * 2048;

    // 256 16B-chunks per plane, 128 threads -> 2 each
    for (int c = tid; c < 256; c += 128) {
        const int qr = c >> 2, qc = (c & 3) * 8;
        *(uint4*)(sQ + qr * QSTR + qc) = *(const uint4*)(Qp + c * 8);
        *(uint4*)(sK + qr * QSTR + qc) = *(const uint4*)(Kp + c * 8);
        const int vr = c >> 3, vc = (c & 7) * 8;
        *(uint4*)(sV + vr * VSTR + vc) = *(const uint4*)(Vp + c * 8);
    }
    for (int t = tid; t < 225; t += 128) bt[t] = bias_table[t * NHEADS + h];
    __syncthreads();

    const int gid = lane >> 2, tig = lane & 3;
    const int a_rowoff = (warp * 16 + (lane & 15)) * QSTR + (lane >> 4) * 8;
    const int b_row    = ((lane >> 4) << 3) + (lane & 7);
    const int b_ksel   = ((lane >> 3) & 1) << 3;

    // ---- QK^T (single-pass fp16) -------------------------------------------
    float acc[8][4];
#pragma unroll
    for (int nt = 0; nt < 8; nt++)
#pragma unroll
        for (int c = 0; c < 4; c++) acc[nt][c] = 0.f;

#pragma unroll
    for (int kt = 0; kt < 2; kt++) {
        uint32_t qf[4];
        ldsm_x4(qf, smem_u32(sQ + a_rowoff + kt * 16));
#pragma unroll
        for (int ng = 0; ng < 4; ng++) {
            uint32_t kf[4];
            const int off = (ng * 16 + b_row) * QSTR + kt * 16 + b_ksel;
            ldsm_x4(kf, smem_u32(sK + off));
#pragma unroll
            for (int j = 0; j < 2; j++)
                mma16816h(acc[ng * 2 + j], qf, &kf[j * 2]);
        }
    }

    // ---- bias + mask ----------------------------------------------------------
    const int i0 = warp * 16 + gid, i1 = i0 + 8;
    const int yi0 = i0 >> 3, xi0 = i0 & 7;
    const int yi1 = i1 >> 3, xi1 = i1 & 7;
    const float* mrow = mask + (size_t)b * 4096;
#pragma unroll
    for (int nt = 0; nt < 8; nt++) {
        const int col = nt * 8 + tig * 2;
        const float2 m0 = *(const float2*)(mrow + i0 * 64 + col);
        const float2 m1 = *(const float2*)(mrow + i1 * 64 + col);
        acc[nt][0] += bt[(yi0 - nt + 7) * 15 + (xi0 - tig * 2 + 7)] + m0.x;
        acc[nt][1] += bt[(yi0 - nt + 7) * 15 + (xi0 - tig * 2 + 6)] + m0.y;
        acc[nt][2] += bt[(yi1 - nt + 7) * 15 + (xi1 - tig * 2 + 7)] + m1.x;
        acc[nt][3] += bt[(yi1 - nt + 7) * 15 + (xi1 - tig * 2 + 6)] + m1.y;
    }

    // ---- softmax ---------------------------------------------------------------
    float mx0 = -1e30f, mx1 = -1e30f;
#pragma unroll
    for (int nt = 0; nt < 8; nt++) {
        mx0 = fmaxf(mx0, fmaxf(acc[nt][0], acc[nt][1]));
        mx1 = fmaxf(mx1, fmaxf(acc[nt][2], acc[nt][3]));
    }
    mx0 = fmaxf(mx0, __shfl_xor_sync(0xffffffffu, mx0, 1));
    mx0 = fmaxf(mx0, __shfl_xor_sync(0xffffffffu, mx0, 2));
    mx1 = fmaxf(mx1, __shfl_xor_sync(0xffffffffu, mx1, 1));
    mx1 = fmaxf(mx1, __shfl_xor_sync(0xffffffffu, mx1, 2));

    float sum0 = 0.f, sum1 = 0.f;
#pragma unroll
    for (int nt = 0; nt < 8; nt++) {
        acc[nt][0] = __expf(acc[nt][0] - mx0);
        acc[nt][1] = __expf(acc[nt][1] - mx0);
        acc[nt][2] = __expf(acc[nt][2] - mx1);
        acc[nt][3] = __expf(acc[nt][3] - mx1);
        sum0 += acc[nt][0] + acc[nt][1];
        sum1 += acc[nt][2] + acc[nt][3];
    }
    sum0 += __shfl_xor_sync(0xffffffffu, sum0, 1);
    sum0 += __shfl_xor_sync(0xffffffffu, sum0, 2);
    sum1 += __shfl_xor_sync(0xffffffffu, sum1, 1);
    sum1 += __shfl_xor_sync(0xffffffffu, sum1, 2);
    const float inv0 = 1.f / sum0, inv1 = 1.f / sum1;

    // ---- P fragments (fp16) -----------------------------------------------------
    uint32_t pf[4][4];
#pragma unroll
    for (int kt = 0; kt < 4; kt++) {
        pf[kt][0] = pack_half2(acc[kt*2][0] * inv0,   acc[kt*2][1] * inv0);
        pf[kt][1] = pack_half2(acc[kt*2][2] * inv1,   acc[kt*2][3] * inv1);
        pf[kt][2] = pack_half2(acc[kt*2+1][0] * inv0, acc[kt*2+1][1] * inv0);
        pf[kt][3] = pack_half2(acc[kt*2+1][2] * inv1, acc[kt*2+1][3] * inv1);
    }

    // ---- P * V (single-pass fp16) -------------------------------------------------
    float ao[4][4];
#pragma unroll
    for (int dn = 0; dn < 4; dn++)
#pragma unroll
        for (int c = 0; c < 4; c++) ao[dn][c] = 0.f;

#pragma unroll
    for (int kt = 0; kt < 4; kt++) {
#pragma unroll
        for (int g = 0; g < 2; g++) {
            uint32_t vf[4];
            const int off = (g * 16 + b_row) * VSTR + kt * 16 + b_ksel;
            ldsm_x4(vf, smem_u32(sV + off));
#pragma unroll
            for (int j = 0; j < 2; j++)
                mma16816h(ao[g * 2 + j], pf[kt], &vf[j * 2]);
        }
    }

    // ---- epilogue: fp16 ao plane for the fp16 proj GEMM -------------------------
#pragma unroll
    for (int dn = 0; dn < 4; dn++) {
        const int d = dn * 8 + tig * 2;
#pragma unroll
        for (int rs = 0; rs < 2; rs++) {
            const int row = rs ? i1 : i0;
            const size_t o = ((size_t)b * 64 + row) * DIM + h * 32 + d;
            *(__half2*)(g_aoh + o) =
                __floats2half2_rn(ao[dn][rs * 2 + 0], ao[dn][rs * 2 + 1]);
        }
    }
}

// ---------------- launch ----------------------------------------------------
extern "C" void kernel_launch(void* const* d_in, const int* in_sizes, int n_in,
                              void* d_out, int out_size)
{
    const float* x          = (const float*)d_in[0]; // (2048,64,256)
    const float* mask       = (const float*)d_in[1]; // (2048,1,64,64)
    const float* w_qkv      = (const float*)d_in[2]; // (768,256)
    const float* b_qkv      = (const float*)d_in[3]; // (768)
    const float* w_proj     = (const float*)d_in[4]; // (256,256)
    const float* b_proj     = (const float*)d_in[5]; // (256)
    const float* bias_table = (const float*)d_in[6]; // (225,8)
    float* out = (float*)d_out;                      // (2048,64,256)

    (void)in_sizes; (void)n_in; (void)out_size;

    __half *xh, *aoh, *wqh, *wph;
    cudaGetSymbolAddress((void**)&xh,  g_xh);
    cudaGetSymbolAddress((void**)&aoh, g_aoh);
    cudaGetSymbolAddress((void**)&wqh, g_wqh);
    cudaGetSymbolAddress((void**)&wph, g_wph);

    cudaFuncSetAttribute(gemm_fp16<0>, cudaFuncAttributeMaxDynamicSharedMemorySize, HGEMM_SMEM);
    cudaFuncSetAttribute(gemm_fp16<1>, cudaFuncAttributeMaxDynamicSharedMemorySize, HGEMM_SMEM);

    // 0) fp32 -> fp16 converts
    {
        int n4 = (MROWS * DIM) / 4;
        convert_half<<<(n4 + 255) / 256, 256>>>(x, xh, n4);
        int w4 = (QKVDIM * DIM) / 4;
        convert_half<<<(w4 + 255) / 256, 256>>>(w_qkv, wqh, w4);
        int p4 = (DIM * DIM) / 4;
        convert_half<<<(p4 + 255) / 256, 256>>>(w_proj, wph, p4);
    }
    // 1) QKV GEMM (fp16) -> q/k/vt fp16 planes (q pre-scaled)
    {
        dim3 grid(QKVDIM / 128, MROWS / 128);   // 6 x 1024
        gemm_fp16<0><<<grid, 256, HGEMM_SMEM>>>(xh, wqh, b_qkv, nullptr);
    }
    // 2) windowed attention (fp16 single-pass) -> g_aoh
    attn_mma<<<B_WIN * NHEADS, 128>>>(mask, bias_table);
    // 3) output projection (fp16) -> out
    {
        dim3 grid(DIM / 128, MROWS / 128);      // 2 x 1024
        gemm_fp16<1><<<grid, 256, HGEMM_SMEM>>>(aoh, wph, b_proj, out);
    }
}